// round 3
// baseline (speedup 1.0000x reference)
#include <cuda_runtime.h>

// ---------------------------------------------------------------------------
// MSDeformAttn fusion: value conv -> off/attn conv -> flow-guided deformable
// sampling -> output conv.  B=2, T=3, C=256, H=W=64, M=8, P=4, DH=32.
// All scratch in __device__ globals (no allocation). 4 sequential launches,
// graph-capturable.
// ---------------------------------------------------------------------------

#define NB   2
#define NT   3
#define NC   256
#define NH   64
#define NW   64
#define NHW  4096
#define NM   8
#define NP   4
#define NDH  32

// Scratch (zero-init .bss, not allocations)
__device__ __align__(16) float g_value[NB*NT*NHW*NC];     // NHWC per (b,t): 25.2 MB
__device__ __align__(16) float g_offattn[NB*NHW*288];     // per-pixel 192 off + 96 attn
__device__ __align__(16) float g_attnout[NB*NC*NHW];      // NCHW attention output

// ---- packed f32x2 helpers (sm_103a dual-rate fp32 path; PTX-only) ----------
__device__ __forceinline__ unsigned long long pack2(float a, float b) {
    union { float2 f; unsigned long long u; } t; t.f = make_float2(a, b); return t.u;
}
__device__ __forceinline__ float2 unpack2(unsigned long long v) {
    union { float2 f; unsigned long long u; } t; t.u = v; return t.f;
}
__device__ __forceinline__ void ffma2(unsigned long long& d,
                                      unsigned long long a, unsigned long long b) {
#if defined(__CUDA_ARCH__) && (__CUDA_ARCH__ >= 1000)
    asm("fma.rn.f32x2 %0, %1, %2, %0;" : "+l"(d) : "l"(a), "l"(b));
#else
    float2 df = unpack2(d), af = unpack2(a), bf = unpack2(b);
    df.x = fmaf(af.x, bf.x, df.x); df.y = fmaf(af.y, bf.y, df.y);
    d = pack2(df.x, df.y);
#endif
}

// ---------------------------------------------------------------------------
// Direct 3x3 SAME conv, NCHW input, fp32, register-blocked 2x2 px * 4 couts
// per thread, f32x2 packed accumulators (co pairs).
// Block: 256 threads = 16x16 output pixel tile x 16 output channels.
//   thread: cog = tid&3 (couts cog*4..+3), quad = tid>>2 -> 2x2 pixel quad.
// MODE 0: value conv  (in=input_flatten as 6x256 imgs) -> g_value NHWC + mask
// MODE 1: off+attn conv (in=query as 2x768 imgs), 18 cout groups:
//         groups 0..11 -> w_off(192ch), 12..17 -> w_attn(96ch); out g_offattn
// MODE 2: out conv (in=g_attnout, 2x256 imgs) -> gout NCHW (final d_out)
// ---------------------------------------------------------------------------
template<int CIN, int MODE>
__global__ __launch_bounds__(256)
void conv3x3(const float* __restrict__ gin,
             const float* __restrict__ w0, const float* __restrict__ b0,
             const float* __restrict__ w1, const float* __restrict__ b1,
             float* __restrict__ gout,
             const unsigned char* __restrict__ mask)
{
    constexpr int NCG = (MODE == 1) ? 18 : 16;
    const int img = blockIdx.z / NCG;
    const int zg  = blockIdx.z % NCG;
    const int tx0 = blockIdx.x * 16;
    const int ty0 = blockIdx.y * 16;
    const int tid = threadIdx.x;
    const int cog  = tid & 3;
    const int quad = tid >> 2;
    const int px0 = (quad & 7) * 2;
    const int py0 = (quad >> 3) * 2;

    const float* wsrc; const float* bsrc; int corow0;
    if (MODE == 1 && zg >= 12) { wsrc = w1; bsrc = b1; corow0 = zg*16 - 192; }
    else                       { wsrc = w0; bsrc = b0; corow0 = zg*16;       }

    const float* src    = (MODE == 2) ? (const float*)g_attnout : gin;
    const float* inbase = src + (size_t)img * CIN * NHW;

    __shared__ float s_in[8][18][20];   // [cin8][y 18][x 18 (+pad)]
    __shared__ float s_w[8*9*16];       // [(ci*9+tap)*16 + co]

    unsigned long long acc[4][2];
    {
        const float* bp = bsrc + corow0 + cog*4;
        unsigned long long p01 = pack2(bp[0], bp[1]);
        unsigned long long p23 = pack2(bp[2], bp[3]);
        #pragma unroll
        for (int p = 0; p < 4; p++) { acc[p][0] = p01; acc[p][1] = p23; }
    }

    for (int cin0 = 0; cin0 < CIN; cin0 += 8) {
        // stage input halo patch 18x18 x 8 cin
        for (int i = tid; i < 8*324; i += 256) {
            int ci = i / 324; int r = i - ci*324;
            int yy = r / 18;  int xx = r - yy*18;
            int gy = ty0 + yy - 1, gx = tx0 + xx - 1;
            float v = 0.f;
            if ((unsigned)gy < 64u && (unsigned)gx < 64u)
                v = inbase[(size_t)(cin0 + ci) * NHW + gy*64 + gx];
            s_in[ci][yy][xx] = v;
        }
        // stage weights: 16 couts x 8 cin x 9 taps, repacked co-contiguous
        for (int i = tid; i < 16*72; i += 256) {
            int co = i / 72; int r = i - co*72;            // r = ci*9 + tap
            s_w[r*16 + co] = wsrc[(size_t)(corow0 + co) * CIN * 9 + cin0*9 + r];
        }
        __syncthreads();

        for (int ci = 0; ci < 8; ci++) {
            #pragma unroll
            for (int tap = 0; tap < 9; tap++) {
                const int dy = tap / 3, dx = tap % 3;
                const float* wp = &s_w[(ci*9 + tap)*16 + cog*4];
                unsigned long long w01 = *reinterpret_cast<const unsigned long long*>(wp);
                unsigned long long w23 = *reinterpret_cast<const unsigned long long*>(wp + 2);
                #pragma unroll
                for (int iy = 0; iy < 2; iy++) {
                    #pragma unroll
                    for (int ix = 0; ix < 2; ix++) {
                        float v = s_in[ci][py0 + dy + iy][px0 + dx + ix];
                        unsigned long long vv = pack2(v, v);
                        ffma2(acc[iy*2 + ix][0], vv, w01);
                        ffma2(acc[iy*2 + ix][1], vv, w23);
                    }
                }
            }
        }
        __syncthreads();
    }

    #pragma unroll
    for (int p = 0; p < 4; p++) {
        const int gy = ty0 + py0 + (p >> 1);
        const int gx = tx0 + px0 + (p & 1);
        float2 a01 = unpack2(acc[p][0]);
        float2 a23 = unpack2(acc[p][1]);
        float4 v4 = make_float4(a01.x, a01.y, a23.x, a23.y);
        if (MODE == 0) {
            size_t pidx = (size_t)img * NHW + gy*64 + gx;  // img = b*T + t
            if (mask[pidx]) v4 = make_float4(0.f, 0.f, 0.f, 0.f);
            *reinterpret_cast<float4*>(&g_value[pidx*NC + zg*16 + cog*4]) = v4;
        } else if (MODE == 1) {
            size_t base = ((size_t)img * NHW + gy*64 + gx) * 288 + zg*16 + cog*4;
            *reinterpret_cast<float4*>(&g_offattn[base]) = v4;
        } else {
            const int co = zg*16 + cog*4;
            size_t base = ((size_t)img * NC + co) * NHW + gy*64 + gx;
            gout[base]            = v4.x;
            gout[base +   NHW]    = v4.y;
            gout[base + 2*NHW]    = v4.z;
            gout[base + 3*NHW]    = v4.w;
        }
    }
}

// ---------------------------------------------------------------------------
// Deformable sampling.  One warp per (b, pixel, head); lane = head channel.
// softmax over T*P=12, flow-guided locations, bilinear zero-pad gather from
// g_value (NHWC -> 128B coalesced per corner), write NCHW g_attnout.
// ---------------------------------------------------------------------------
__global__ __launch_bounds__(256)
void deform_sample(const float* __restrict__ ref,
                   const float* __restrict__ flow_f,
                   const float* __restrict__ flow_b)
{
    const int wg   = blockIdx.x * 8 + (threadIdx.x >> 5);
    const int lane = threadIdx.x & 31;
    const int m   = wg & 7;
    const int pix = (wg >> 3) & 4095;
    const int b   = wg >> 15;

    const float* oa = g_offattn + (size_t)(b * NHW + pix) * 288;

    // softmax over the 12 (t,p) attention logits of this head
    float att[12];
    float mx = -1e30f;
    #pragma unroll
    for (int i = 0; i < 12; i++) { att[i] = oa[192 + m*12 + i]; mx = fmaxf(mx, att[i]); }
    float s = 0.f;
    #pragma unroll
    for (int i = 0; i < 12; i++) { att[i] = __expf(att[i] - mx); s += att[i]; }
    const float inv = 1.0f / s;
    #pragma unroll
    for (int i = 0; i < 12; i++) att[i] *= inv;

    float acc = 0.f;
    const float* vb = g_value + (size_t)(b * NT) * NHW * NC + m*NDH + lane;
    const float* rp = ref + (size_t)(b * NHW + pix) * (NT*2);

    #pragma unroll
    for (int t = 0; t < NT; t++) {
        // flow: t=0 <- flow_backward[b,0,:], t=1 <- 0, t=2 <- flow_forward[b,1,:]
        float fx = 0.f, fy = 0.f;
        if (t == 0) { fx = flow_b[b*16384 + pix];        fy = flow_b[b*16384 + 4096 + pix]; }
        if (t == 2) { fx = flow_f[b*16384 + 8192 + pix]; fy = flow_f[b*16384 + 8192 + 4096 + pix]; }
        // sample coord = ref*W + off + flow - 0.5  (normalizer W=H=64 cancels)
        const float rx = rp[t*2 + 0] * 64.f - 0.5f + fx;
        const float ry = rp[t*2 + 1] * 64.f - 0.5f + fy;
        const float* vt = vb + (size_t)t * NHW * NC;
        #pragma unroll
        for (int p = 0; p < NP; p++) {
            const float sx = rx + oa[(m*NT + t)*8 + p*2 + 0];
            const float sy = ry + oa[(m*NT + t)*8 + p*2 + 1];
            const float x0f = floorf(sx), y0f = floorf(sy);
            const float wx = sx - x0f, wy = sy - y0f;
            const int x0 = (int)x0f, y0 = (int)y0f;
            const float a = att[t*4 + p];
            const float w00 = (1.f - wx) * (1.f - wy) * a;
            const float w10 = wx * (1.f - wy) * a;
            const float w01 = (1.f - wx) * wy * a;
            const float w11 = wx * wy * a;
            const bool xv0 = (unsigned)x0       < 64u;
            const bool xv1 = (unsigned)(x0 + 1) < 64u;
            if ((unsigned)y0 < 64u) {
                const float* r0 = vt + (size_t)(y0*64) * NC;
                if (xv0) acc += w00 * r0[(size_t)x0 * NC];
                if (xv1) acc += w10 * r0[(size_t)(x0 + 1) * NC];
            }
            if ((unsigned)(y0 + 1) < 64u) {
                const float* r1 = vt + (size_t)((y0 + 1)*64) * NC;
                if (xv0) acc += w01 * r1[(size_t)x0 * NC];
                if (xv1) acc += w11 * r1[(size_t)(x0 + 1) * NC];
            }
        }
    }
    g_attnout[(size_t)(b*NC + m*NDH + lane) * NHW + pix] = acc;
}

// ---------------------------------------------------------------------------
// metadata order:
// 0 query (B,T,C,H,W) 1 reference_points (B,HW,T,2) 2 input_flatten (B,T,C,H,W)
// 3 spatial_shapes 4 level_start 5 padding_mask(bool) 6 flow_forward (B,2,2,H,W)
// 7 flow_backward 8 w_value 9 b_value 10 w_off 11 b_off 12 w_attn 13 b_attn
// 14 w_out 15 b_out ; out (B,C,H,W) f32
// ---------------------------------------------------------------------------
extern "C" void kernel_launch(void* const* d_in, const int* in_sizes, int n_in,
                              void* d_out, int out_size)
{
    const float* query         = (const float*)d_in[0];
    const float* refp          = (const float*)d_in[1];
    const float* input_flatten = (const float*)d_in[2];
    const unsigned char* mask  = (const unsigned char*)d_in[5];
    const float* flow_f        = (const float*)d_in[6];
    const float* flow_b        = (const float*)d_in[7];
    const float* w_value       = (const float*)d_in[8];
    const float* b_value       = (const float*)d_in[9];
    const float* w_off         = (const float*)d_in[10];
    const float* b_off         = (const float*)d_in[11];
    const float* w_attn        = (const float*)d_in[12];
    const float* b_attn        = (const float*)d_in[13];
    const float* w_out         = (const float*)d_in[14];
    const float* b_out         = (const float*)d_in[15];
    float* out = (float*)d_out;

    // 1) value conv: 6 images of 256ch -> g_value NHWC (+mask)
    conv3x3<256, 0><<<dim3(4, 4, 6*16), 256>>>(input_flatten, w_value, b_value,
                                               nullptr, nullptr, nullptr, mask);
    // 2) fused offset(192)+attn(96) conv: 2 images of 768ch -> g_offattn
    conv3x3<768, 1><<<dim3(4, 4, 2*18), 256>>>(query, w_off, b_off,
                                               w_attn, b_attn, nullptr, nullptr);
    // 3) deformable sampling: 65536 warps -> g_attnout NCHW
    deform_sample<<<8192, 256>>>(refp, flow_f, flow_b);
    // 4) output conv: 2 images of 256ch -> final d_out NCHW
    conv3x3<256, 2><<<dim3(4, 4, 2*16), 256>>>(nullptr, w_out, b_out,
                                               nullptr, nullptr, out, nullptr);
}